// round 1
// baseline (speedup 1.0000x reference)
#include <cuda_runtime.h>

// Inputs (metadata order): query_points [N,3] f32, ref_points [M,3] f32, ref_flow [M,3] f32
// Output: [N,3] f32
// N = 32768, M = 16384 for this problem (kept runtime-general up to MMAX).

#define MMAX 16384
#define TILE 2048
#define KNN 8

// Packed refs: (x, y, z, |r|^2). Device-global scratch (no allocation allowed).
__device__ float4 g_refs[MMAX];

__global__ void prep_refs_kernel(const float* __restrict__ ref, int M) {
    int i = blockIdx.x * blockDim.x + threadIdx.x;
    if (i < M) {
        float x = ref[3 * i + 0];
        float y = ref[3 * i + 1];
        float z = ref[3 * i + 2];
        float r2 = fmaf(x, x, fmaf(y, y, z * z));
        g_refs[i] = make_float4(x, y, z, r2);
    }
}

__global__ void __launch_bounds__(256) knn_idw_kernel(
    const float* __restrict__ qpts,
    const float* __restrict__ flow,
    float* __restrict__ out,
    int N, int M)
{
    __shared__ float4 s_ref[TILE];

    int qi = blockIdx.x * blockDim.x + threadIdx.x;

    float qx = 0.f, qy = 0.f, qz = 0.f;
    if (qi < N) {
        qx = qpts[3 * qi + 0];
        qy = qpts[3 * qi + 1];
        qz = qpts[3 * qi + 2];
    }
    // score(r) = |r|^2 - 2 q.r  (monotone with squared distance; |q|^2 added later)
    const float nqx = -2.0f * qx;
    const float nqy = -2.0f * qy;
    const float nqz = -2.0f * qz;

    // Sorted ascending top-8 (bd[7] = current worst kept)
    float bd[KNN];
    int   bi[KNN];
#pragma unroll
    for (int k = 0; k < KNN; ++k) { bd[k] = 3.4e38f; bi[k] = 0; }

    for (int base = 0; base < M; base += TILE) {
        int cnt = min(TILE, M - base);
        __syncthreads();  // protect previous tile's readers before overwrite
        for (int j = threadIdx.x; j < cnt; j += blockDim.x) {
            s_ref[j] = g_refs[base + j];
        }
        __syncthreads();

#pragma unroll 4
        for (int j = 0; j < cnt; ++j) {
            float4 r = s_ref[j];  // broadcast across the warp (conflict-free)
            float s = fmaf(r.x, nqx, fmaf(r.y, nqy, fmaf(r.z, nqz, r.w)));
            if (s < bd[KNN - 1]) {
                bd[KNN - 1] = s;
                bi[KNN - 1] = base + j;
                // single bubble pass restores sorted order (array was sorted)
#pragma unroll
                for (int k = KNN - 1; k > 0; --k) {
                    if (bd[k] < bd[k - 1]) {
                        float td = bd[k]; bd[k] = bd[k - 1]; bd[k - 1] = td;
                        int   ti = bi[k]; bi[k] = bi[k - 1]; bi[k - 1] = ti;
                    }
                }
            }
        }
    }

    if (qi >= N) return;

    // IDW with POWER=2: weight = 1 / (max(d2, 0) + 1e-8); d2 = |q|^2 + score.
    // (sqrt then ^2 in the reference is an exact no-op up to ~2ulp, far below 1e-3.)
    float q2 = fmaf(qx, qx, fmaf(qy, qy, qz * qz));
    float wsum = 0.f, ox = 0.f, oy = 0.f, oz = 0.f;
#pragma unroll
    for (int k = 0; k < KNN; ++k) {
        float d2 = fmaxf(q2 + bd[k], 0.0f);
        float w = 1.0f / (d2 + 1e-8f);
        int id = bi[k];
        ox = fmaf(w, flow[3 * id + 0], ox);
        oy = fmaf(w, flow[3 * id + 1], oy);
        oz = fmaf(w, flow[3 * id + 2], oz);
        wsum += w;
    }
    float inv = 1.0f / wsum;
    out[3 * qi + 0] = ox * inv;
    out[3 * qi + 1] = oy * inv;
    out[3 * qi + 2] = oz * inv;
}

extern "C" void kernel_launch(void* const* d_in, const int* in_sizes, int n_in,
                              void* d_out, int out_size) {
    const float* q = (const float*)d_in[0];
    const float* r = (const float*)d_in[1];
    const float* f = (const float*)d_in[2];
    int N = in_sizes[0] / 3;
    int M = in_sizes[1] / 3;
    if (M > MMAX) M = MMAX;  // scratch bound (problem shape is M=16384)

    prep_refs_kernel<<<(M + 255) / 256, 256>>>(r, M);
    knn_idw_kernel<<<(N + 255) / 256, 256>>>(q, f, (float*)d_out, N, M);
}

// round 2
// speedup vs baseline: 1.2465x; 1.2465x over previous
#include <cuda_runtime.h>
#include <math_constants.h>

// Inputs (metadata order): query_points [N,3] f32, ref_points [M,3] f32, ref_flow [M,3] f32
// Output: [N,3] f32.  Problem shape: N=32768, M=16384 (kept general up to the bounds below).

#define NMAX  32768
#define MMAX  16384
#define TILE  1024          // candidates per smem tile (16 KB of float4)
#define KNN   8
#define SPLIT 8             // M-dimension split for occupancy

// Packed refs: (x, y, z, |r|^2).
__device__ float4 g_refs[MMAX];
// Partial top-K per (split, k, query) — [SPLIT][KNN][NMAX] layout so phase-2 reads
// are coalesced over query id and phase-1 writes are coalesced over threads.
__device__ float g_ps[SPLIT][KNN][NMAX];
__device__ int   g_pi[SPLIT][KNN][NMAX];

__global__ void prep_refs_kernel(const float* __restrict__ ref, int M) {
    int i = blockIdx.x * blockDim.x + threadIdx.x;
    if (i < M) {
        float x = ref[3 * i + 0];
        float y = ref[3 * i + 1];
        float z = ref[3 * i + 2];
        g_refs[i] = make_float4(x, y, z, fmaf(x, x, fmaf(y, y, z * z)));
    }
}

// Phase 1: each block handles 256 queries x one M-slice. score = |r|^2 - 2 q.r
// (monotone with squared distance; |q|^2 added in phase 2).
__global__ void __launch_bounds__(256) knn_partial_kernel(
    const float* __restrict__ qpts, int N, int M)
{
    __shared__ float4 s_ref[TILE];

    const int qi = blockIdx.x * blockDim.x + threadIdx.x;
    const int s  = blockIdx.y;
    const int Ms = (M + SPLIT - 1) / SPLIT;
    const int lo = s * Ms;
    const int hi = min(lo + Ms, M);

    float qx = 0.f, qy = 0.f, qz = 0.f;
    if (qi < N) {
        qx = qpts[3 * qi + 0];
        qy = qpts[3 * qi + 1];
        qz = qpts[3 * qi + 2];
    }
    const float nqx = -2.0f * qx;
    const float nqy = -2.0f * qy;
    const float nqz = -2.0f * qz;

    float bd[KNN];
    int   bi[KNN];
#pragma unroll
    for (int k = 0; k < KNN; ++k) { bd[k] = CUDART_INF_F; bi[k] = 0; }

    for (int base = lo; base < hi; base += TILE) {
        int cnt = min(TILE, hi - base);
        __syncthreads();
        for (int j = threadIdx.x; j < TILE; j += blockDim.x) {
            // pad tail with +inf score so group-of-4 logic needs no bounds checks
            s_ref[j] = (j < cnt) ? g_refs[base + j]
                                 : make_float4(0.f, 0.f, 0.f, CUDART_INF_F);
        }
        __syncthreads();

#pragma unroll 2
        for (int j = 0; j < TILE; j += 4) {
            float4 r0 = s_ref[j + 0];
            float4 r1 = s_ref[j + 1];
            float4 r2 = s_ref[j + 2];
            float4 r3 = s_ref[j + 3];
            float s0 = fmaf(r0.x, nqx, fmaf(r0.y, nqy, fmaf(r0.z, nqz, r0.w)));
            float s1 = fmaf(r1.x, nqx, fmaf(r1.y, nqy, fmaf(r1.z, nqz, r1.w)));
            float s2 = fmaf(r2.x, nqx, fmaf(r2.y, nqy, fmaf(r2.z, nqz, r2.w)));
            float s3 = fmaf(r3.x, nqx, fmaf(r3.y, nqy, fmaf(r3.z, nqz, r3.w)));
            float m = fminf(fminf(s0, s1), fminf(s2, s3));
            if (m < bd[KNN - 1]) {   // rare path: one guard per 4 candidates
                float sv[4] = {s0, s1, s2, s3};
#pragma unroll
                for (int t = 0; t < 4; ++t) {
                    if (sv[t] < bd[KNN - 1]) {
                        bd[KNN - 1] = sv[t];
                        bi[KNN - 1] = base + j + t;
#pragma unroll
                        for (int k = KNN - 1; k > 0; --k) {
                            if (bd[k] < bd[k - 1]) {
                                float td = bd[k]; bd[k] = bd[k - 1]; bd[k - 1] = td;
                                int   ti = bi[k]; bi[k] = bi[k - 1]; bi[k - 1] = ti;
                            }
                        }
                    }
                }
            }
        }
    }

    if (qi < N) {
#pragma unroll
        for (int k = 0; k < KNN; ++k) {
            g_ps[s][k][qi] = bd[k];
            g_pi[s][k][qi] = bi[k];
        }
    }
}

// Phase 2: merge SPLIT partial lists (SPLIT*KNN = 64 candidates), IDW epilogue.
__global__ void __launch_bounds__(256) knn_merge_kernel(
    const float* __restrict__ qpts,
    const float* __restrict__ flow,
    float* __restrict__ out, int N)
{
    int qi = blockIdx.x * blockDim.x + threadIdx.x;
    if (qi >= N) return;

    float bd[KNN];
    int   bi[KNN];
#pragma unroll
    for (int k = 0; k < KNN; ++k) { bd[k] = CUDART_INF_F; bi[k] = 0; }

#pragma unroll
    for (int s = 0; s < SPLIT; ++s) {
#pragma unroll
        for (int k = 0; k < KNN; ++k) {
            float v = g_ps[s][k][qi];
            if (v < bd[KNN - 1]) {
                bd[KNN - 1] = v;
                bi[KNN - 1] = g_pi[s][k][qi];
#pragma unroll
                for (int t = KNN - 1; t > 0; --t) {
                    if (bd[t] < bd[t - 1]) {
                        float td = bd[t]; bd[t] = bd[t - 1]; bd[t - 1] = td;
                        int   ti = bi[t]; bi[t] = bi[t - 1]; bi[t - 1] = ti;
                    }
                }
            }
        }
    }

    float qx = qpts[3 * qi + 0];
    float qy = qpts[3 * qi + 1];
    float qz = qpts[3 * qi + 2];
    float q2 = fmaf(qx, qx, fmaf(qy, qy, qz * qz));

    // IDW, POWER=2: w = 1/(max(d2,0)+1e-8); d2 = |q|^2 + score.
    float wsum = 0.f, ox = 0.f, oy = 0.f, oz = 0.f;
#pragma unroll
    for (int k = 0; k < KNN; ++k) {
        float d2 = fmaxf(q2 + bd[k], 0.0f);
        float w = 1.0f / (d2 + 1e-8f);
        int id = bi[k];
        ox = fmaf(w, flow[3 * id + 0], ox);
        oy = fmaf(w, flow[3 * id + 1], oy);
        oz = fmaf(w, flow[3 * id + 2], oz);
        wsum += w;
    }
    float inv = 1.0f / wsum;
    out[3 * qi + 0] = ox * inv;
    out[3 * qi + 1] = oy * inv;
    out[3 * qi + 2] = oz * inv;
}

extern "C" void kernel_launch(void* const* d_in, const int* in_sizes, int n_in,
                              void* d_out, int out_size) {
    const float* q = (const float*)d_in[0];
    const float* r = (const float*)d_in[1];
    const float* f = (const float*)d_in[2];
    int N = in_sizes[0] / 3;
    int M = in_sizes[1] / 3;
    if (M > MMAX) M = MMAX;
    if (N > NMAX) N = NMAX;

    prep_refs_kernel<<<(M + 255) / 256, 256>>>(r, M);
    dim3 grid1((N + 255) / 256, SPLIT);
    knn_partial_kernel<<<grid1, 256>>>(q, N, M);
    knn_merge_kernel<<<(N + 255) / 256, 256>>>(q, f, (float*)d_out, N);
}